// round 16
// baseline (speedup 1.0000x reference)
#include <cuda_runtime.h>
#include <cuda_bf16.h>
#include <cuda_fp16.h>

#define NATOMS 256
#define PDIM 2
#define LDIM 9
#define FDIM 64
#define ROWLEN (PDIM*LDIM*FDIM)                 // 1152
#define GK (NATOMS*ROWLEN)                      // 294912
#define NROWS_TOTAL (NATOMS*NATOMS*PDIM*LDIM)   // 1,179,648 rows of 64
#define HROWS (NROWS_TOTAL/2)
#define PHROWS (NATOMS*LDIM)                    // 2304 parity-local rows per atom

// ---------------- scratch ------------------------------------------------------
__device__ __half g_Th[NATOMS * GK];            // fp16 T = x @ M
__device__ __half g_xh[NATOMS * GK];            // fp16 x
__device__ float  g_M[PDIM * FDIM * FDIM];      // fp32 M (exact recompute)
__device__ __half g_Mt16 [PDIM * FDIM * FDIM];  // Mt[p][f][e] fp16
__device__ __half g_Wvt16[PDIM * FDIM * FDIM];  // Wvt[p][f][e] fp16
__device__ float g_dotb[NATOMS * NATOMS];
__device__ float g_cmax[NATOMS];
__device__ float g_csum[NATOMS];
__device__ int   g_idx[NATOMS * NATOMS];
__device__ float g_wval[NATOMS * NATOMS];
__device__ int   g_nnz[NATOMS];
__device__ int   g_ccol[NATOMS];
__device__ int   g_calist[NATOMS * 8];
__device__ int   g_cak[NATOMS];
__device__ int   g_nccols;

extern __shared__ __half smdyn[];

// ---------------- K0 ------------------------------------------------------------
__global__ void k0_zero() {
    int i = blockIdx.x * blockDim.x + threadIdx.x;
    if (i < NATOMS * NATOMS) g_dotb[i] = 0.0f;
    if (i < NATOMS) g_nnz[i] = 0;
    if (i == 0) g_nccols = 0;
}

// ---------------- K1: M fp32 + Mt/Wvt fp16 transposed ----------------------------
__global__ void k1_M(const float* __restrict__ Wq, const float* __restrict__ Wk,
                     const float* __restrict__ Wv) {
    int id = blockIdx.x * blockDim.x + threadIdx.x;
    if (id >= PDIM * FDIM * FDIM) return;
    int p = id >> 12;
    int e = (id >> 6) & 63;
    int f = id & 63;
    const float* q = Wq + (p << 12) + (e << 6);
    const float* k = Wk + (p << 12) + (f << 6);
    float s = 0.0f;
#pragma unroll 16
    for (int g = 0; g < 64; g++) s += q[g] * k[g];
    g_M[id] = s;

    int tid = (p << 12) + (f << 6) + e;   // transposed [p][f][e]
    g_Mt16[tid]  = __float2half_rn(s);
    g_Wvt16[tid] = __float2half_rn(Wv[id]);
}

// ---------------- helpers --------------------------------------------------------
static __device__ __forceinline__ void cpa16(unsigned sdst, const void* gsrc) {
    asm volatile("cp.async.cg.shared.global [%0], [%1], 16;\n" :: "r"(sdst), "l"(gsrc));
}
static __device__ __forceinline__ void ldsm_x4(unsigned r[4], unsigned addr) {
    asm volatile("ldmatrix.sync.aligned.m8n8.x4.shared.b16 {%0,%1,%2,%3}, [%4];\n"
        : "=r"(r[0]), "=r"(r[1]), "=r"(r[2]), "=r"(r[3]) : "r"(addr));
}
static __device__ __forceinline__ void mma_f16(float d[4], const unsigned a[4],
                                               const unsigned b0, const unsigned b1) {
    asm volatile("mma.sync.aligned.m16n8k16.row.col.f32.f16.f16.f32 "
        "{%0,%1,%2,%3},{%4,%5,%6,%7},{%8,%9},{%0,%1,%2,%3};\n"
        : "+f"(d[0]), "+f"(d[1]), "+f"(d[2]), "+f"(d[3])
        : "r"(a[0]), "r"(a[1]), "r"(a[2]), "r"(a[3]), "r"(b0), "r"(b1));
}
static __device__ __forceinline__ unsigned pack_h2(float a, float b) {
    __half2 h2 = __floats2half2_rn(a, b);
    return *reinterpret_cast<unsigned*>(&h2);
}

#define PB 72   // smem pitch (16-bit elems): 144B rows -> conflict-free ldsm

// ---------------- K2F: parity-sorted T = x@M + xh emit (256 rows/block, occ 3) -----
__global__ __launch_bounds__(256, 3) void k2f(const float* __restrict__ x) {
    __half* mt16 = smdyn;                 // [64][PB]
    __half* x16  = mt16 + 64 * PB;        // [128][PB]
    __half* stgT = x16 + 128 * PB;        // [128][PB]

    const int t = threadIdx.x;
    const int warp = t >> 5, lane = t & 31;
    const int P = blockIdx.y;

    for (int i = t; i < 4096; i += 256) {
        int f = i >> 6, e = i & 63;
        mt16[f * PB + e] = g_Mt16[(P << 12) + i];
    }

    const int rloc = t >> 1;
    const int eh   = (t & 1) * 32;
    const int rowbase = warp * 16;
    const unsigned axoff = ((rowbase + (lane & 15)) * PB + (lane >> 4) * 8) * 2;
    const int lc = (lane & 3) * 2;
    const int raL = rowbase + (lane >> 2);

    const unsigned ux = (unsigned)__cvta_generic_to_shared(x16);
    const unsigned um = (unsigned)__cvta_generic_to_shared(mt16);

    for (int h = 0; h < 2; h++) {
        const int r0 = blockIdx.x * 256 + h * 128;
        __syncthreads();

        size_t grW;
        {
            int g = r0 + rloc;
            int q = g / 9, l = g - 9 * q;
            grW = (size_t)(q * 18 + P * 9 + l);
            const float* gx = x + grW * 64 + eh;
            unsigned hx[16];
#pragma unroll
            for (int qq = 0; qq < 8; qq++) {
                float4 v = *(const float4*)(gx + qq * 4);
                unsigned h01 = pack_h2(v.x, v.y), h23 = pack_h2(v.z, v.w);
                hx[qq * 2] = h01; hx[qq * 2 + 1] = h23;
                *(unsigned*)(x16 + rloc * PB + eh + qq * 4)     = h01;
                *(unsigned*)(x16 + rloc * PB + eh + qq * 4 + 2) = h23;
            }
            uint4* dh = (uint4*)(g_xh + grW * 64 + eh);
#pragma unroll
            for (int qq = 0; qq < 4; qq++)
                dh[qq] = make_uint4(hx[4*qq], hx[4*qq+1], hx[4*qq+2], hx[4*qq+3]);
        }
        __syncthreads();

        float accT[8][4];
#pragma unroll
        for (int n = 0; n < 8; n++)
#pragma unroll
            for (int v = 0; v < 4; v++) accT[n][v] = 0.0f;

#pragma unroll
        for (int k = 0; k < 4; k++) {
            unsigned A[4];
            ldsm_x4(A, ux + axoff + k * 32);
#pragma unroll
            for (int n2 = 0; n2 < 4; n2++) {
                unsigned bo = ((n2 * 16 + (lane & 15)) * PB + (lane >> 4) * 8) * 2 + k * 32;
                unsigned B[4];
                ldsm_x4(B, um + bo);
                mma_f16(accT[2*n2],   A, B[0], B[2]);
                mma_f16(accT[2*n2+1], A, B[1], B[3]);
            }
        }
#pragma unroll
        for (int n = 0; n < 8; n++) {
            int col = n * 8 + lc;
            *(unsigned*)(stgT + raL * PB + col)       = pack_h2(accT[n][0], accT[n][1]);
            *(unsigned*)(stgT + (raL + 8) * PB + col) = pack_h2(accT[n][2], accT[n][3]);
        }
        __syncthreads();
        {
            const uint4* sT = (const uint4*)(stgT + rloc * PB + eh);
            uint4* dT = (uint4*)(g_Th + grW * 64 + eh);
#pragma unroll
            for (int qq = 0; qq < 4; qq++) dT[qq] = sT[qq];
        }
    }
}

// ---------------- K3s: dotb = Th * xh^T (fp16 HMMA; 128x64 tiles, occ 3) ----------
#define K3_KCHUNK 4096
#define K3_STAGES 3                       // each stage = 2 x 16-k pieces (32 k)
#define PITCH 24
#define A_PIECE (128 * PITCH * 2)         // 6144 B
#define B_PIECE (64 * PITCH * 2)          // 3072 B
#define A_STAGE (2 * A_PIECE)             // 12288
#define B_STAGE (2 * B_PIECE)             // 6144

__global__ __launch_bounds__(256, 3) void k3s_dot() {
    __half* As = smdyn;                                   // 3 stages x 2 pieces x [128][PITCH]
    __half* Bs = As + K3_STAGES * (A_STAGE / 2);

    const int t = threadIdx.x;
    const int m0 = blockIdx.x * 128, n0 = blockIdx.y * 64;
    const size_t kb = (size_t)blockIdx.z * K3_KCHUNK;

    const unsigned uA = (unsigned)__cvta_generic_to_shared(As);
    const unsigned uB = (unsigned)__cvta_generic_to_shared(Bs);

    const int row = t >> 1, half = t & 1;
    const __half* ga = g_Th + (size_t)(m0 + row) * GK + kb + half * 8;
    const __half* gb = g_xh + (size_t)(n0 + row) * GK + kb + half * 8;   // valid t<128
    const unsigned soff = (row * PITCH + half * 8) * 2;
    const bool bload = (t < 128);

    const int NS2 = K3_KCHUNK / 32;       // 128 iterations

#define K3_LOAD(sl, st)                                                          \
    do {                                                                          \
        _Pragma("unroll")                                                         \
        for (int p = 0; p < 2; p++) {                                             \
            cpa16(uA + (st) * A_STAGE + p * A_PIECE + soff,                       \
                  ga + (size_t)((sl) * 2 + p) * 16);                              \
            if (bload)                                                            \
                cpa16(uB + (st) * B_STAGE + p * B_PIECE + soff,                   \
                      gb + (size_t)((sl) * 2 + p) * 16);                          \
        }                                                                         \
    } while (0)

    K3_LOAD(0, 0);
    asm volatile("cp.async.commit_group;\n");
    K3_LOAD(1, 1);
    asm volatile("cp.async.commit_group;\n");

    const int warp = t >> 5, lane = t & 31;
    const int wm = warp >> 2, wn = warp & 3;               // 2 x 4: 64m x 16n per warp
    const unsigned aoff = ((wm * 64 + (lane & 15)) * PITCH + (lane >> 4) * 8) * 2;
    const unsigned boff = ((wn * 16 + (lane & 15)) * PITCH + (lane >> 4) * 8) * 2;

    float acc[4][2][4] = {};

    int buf = 0, pbuf = K3_STAGES - 1;
    for (int ks = 0; ks < NS2; ks++) {
        asm volatile("cp.async.wait_group %0;\n" :: "n"(K3_STAGES - 2));
        __syncthreads();

#pragma unroll
        for (int p = 0; p < 2; p++) {
            const unsigned baseA = buf * A_STAGE + p * A_PIECE;
            const unsigned baseB = buf * B_STAGE + p * B_PIECE;
            unsigned bh[4];
            ldsm_x4(bh, uB + boff + baseB);
#pragma unroll
            for (int i = 0; i < 4; i++) {
                unsigned ah[4];
                ldsm_x4(ah, uA + aoff + baseA + i * 16 * PITCH * 2);
                mma_f16(acc[i][0], ah, bh[0], bh[2]);
                mma_f16(acc[i][1], ah, bh[1], bh[3]);
            }
        }

        const int pf = ks + K3_STAGES - 1;
        if (pf < NS2) K3_LOAD(pf, pbuf);
        asm volatile("cp.async.commit_group;\n");
        buf  = (buf  == K3_STAGES - 1) ? 0 : buf  + 1;
        pbuf = (pbuf == K3_STAGES - 1) ? 0 : pbuf + 1;
    }
    asm volatile("cp.async.wait_group 0;\n");

    const int lr = lane >> 2, lc = (lane & 3) * 2;
#pragma unroll
    for (int i = 0; i < 4; i++)
#pragma unroll
        for (int j = 0; j < 2; j++) {
            int r = m0 + wm * 64 + i * 16 + lr;
            int c = n0 + wn * 16 + j * 8 + lc;
            atomicAdd(&g_dotb[r * NATOMS + c],           acc[i][j][0]);
            atomicAdd(&g_dotb[r * NATOMS + c + 1],       acc[i][j][1]);
            atomicAdd(&g_dotb[(r + 8) * NATOMS + c],     acc[i][j][2]);
            atomicAdd(&g_dotb[(r + 8) * NATOMS + c + 1], acc[i][j][3]);
        }
}

// ---------------- K4b: columns with >=2 entries within margin ----------------------
#define CLOSE_MARGIN 14.0f
__global__ void k4b_close() {
    int c = blockIdx.x, t = threadIdx.x;
    __shared__ float red[256];
    __shared__ int cnt, pos;
    if (t == 0) { cnt = 0; pos = 0; }
    float v = g_dotb[t * NATOMS + c];
    red[t] = v; __syncthreads();
    for (int s = 128; s > 0; s >>= 1) {
        if (t < s) red[t] = fmaxf(red[t], red[t + s]);
        __syncthreads();
    }
    float mx = red[0];
    bool cand = (v >= mx - CLOSE_MARGIN);
    if (cand) atomicAdd(&cnt, 1);
    __syncthreads();
    if (cnt >= 2) {
        if (t == 0) { int s = atomicAdd(&g_nccols, 1); g_ccol[s] = c; }
        if (cand) {
            int p = atomicAdd(&pos, 1);
            if (p < 8) { g_calist[c * 8 + p] = t; g_dotb[t * NATOMS + c] = 0.0f; }
        }
        __syncthreads();
        if (t == 0) g_cak[c] = (cnt < 8) ? cnt : 8;
    }
}

// ---------------- K5x: exact fp32 logits for close columns -------------------------
__global__ __launch_bounds__(256) void k5x_exact(const float* __restrict__ x) {
    __shared__ float Msh[2 * 4096];
    __shared__ float red[256];
    int s = blockIdx.y;
    if (s >= g_nccols) return;
    int t = threadIdx.x;
    int c = g_ccol[s];
    int ka = g_cak[c];

    for (int i = t; i < 8192 / 4; i += 256)
        ((float4*)Msh)[i] = ((const float4*)g_M)[i];
    __syncthreads();

    int row = blockIdx.x * 256 + t;
    int p = (row / LDIM) & 1;
    const float* Mp = Msh + (p << 12);

    float xc[64];
    {
        const float4* xcp = (const float4*)(x + (size_t)c * GK + (size_t)row * 64);
#pragma unroll
        for (int i = 0; i < 16; i++) {
            float4 v = xcp[i];
            xc[4*i] = v.x; xc[4*i+1] = v.y; xc[4*i+2] = v.z; xc[4*i+3] = v.w;
        }
    }
    float z[64];
#pragma unroll 4
    for (int e = 0; e < 64; e++) {
        const float4* Mr = (const float4*)(Mp + e * 64);
        float sm = 0.0f;
#pragma unroll
        for (int f4 = 0; f4 < 16; f4++) {
            float4 m = Mr[f4];
            sm += m.x * xc[4*f4] + m.y * xc[4*f4+1] + m.z * xc[4*f4+2] + m.w * xc[4*f4+3];
        }
        z[e] = sm;
    }

    for (int j = 0; j < ka; j++) {
        int a = g_calist[c * 8 + j];
        const float4* xap = (const float4*)(x + (size_t)a * GK + (size_t)row * 64);
        float sd = 0.0f;
#pragma unroll
        for (int i = 0; i < 16; i++) {
            float4 v = xap[i];
            sd += v.x * z[4*i] + v.y * z[4*i+1] + v.z * z[4*i+2] + v.w * z[4*i+3];
        }
        red[t] = sd; __syncthreads();
        for (int st = 128; st > 0; st >>= 1) {
            if (t < st) red[t] += red[t + st];
            __syncthreads();
        }
        if (t == 0) atomicAdd(&g_dotb[a * NATOMS + c], red[0]);
        __syncthreads();
    }
}

// ---------------- K4s: per-column softmax stats (max, sum) -------------------------
__global__ void k4_stats() {
    int c = blockIdx.x, t = threadIdx.x;
    __shared__ float red[256];
    float v = g_dotb[t * NATOMS + c];
    red[t] = v; __syncthreads();
    for (int s = 128; s > 0; s >>= 1) {
        if (t < s) red[t] = fmaxf(red[t], red[t + s]);
        __syncthreads();
    }
    float mx = red[0]; __syncthreads();
    float e = expf(v - mx);
    red[t] = e; __syncthreads();
    for (int s = 128; s > 0; s >>= 1) {
        if (t < s) red[t] += red[t + s];
        __syncthreads();
    }
    if (t == 0) { g_cmax[c] = mx; g_csum[c] = red[0]; }
}

// ---------------- K5: compact significant weights (softmax inline) -----------------
__global__ void k5_compact() {
    int a = blockIdx.x, t = threadIdx.x;
    float wv = expf(g_dotb[a * NATOMS + t] - g_cmax[t]) / g_csum[t];
    bool nz = (wv > 1e-7f);
    unsigned m = __ballot_sync(0xffffffffu, nz);
    int lane = t & 31, warp = t >> 5;
    int pre = __popc(m & ((1u << lane) - 1u));
    __shared__ int wcnt[8], woff[8];
    if (lane == 0) wcnt[warp] = __popc(m);
    __syncthreads();
    if (t == 0) {
        int s = 0;
        for (int i = 0; i < 8; i++) { woff[i] = s; s += wcnt[i]; }
        g_nnz[a] = s;
    }
    __syncthreads();
    if (nz) {
        int pos = woff[warp] + pre;
        g_idx[a * NATOMS + pos]  = t;
        g_wval[a * NATOMS + pos] = wv;
    }
}

// ---------------- K6Y: out[a] = (sum_j w_j xh[b_j]) @ Wv  (256 rows/block, occ 3) ---
#define FPITCH 68   // fp32 staging pitch

__global__ __launch_bounds__(256, 3) void k6y(float* __restrict__ out) {
    __half* wv16 = smdyn;                  // [64][PB]
    __half* y16  = wv16 + 64 * PB;         // [128][PB]
    float*  stgF = (float*)(y16 + 128 * PB);   // [128][FPITCH]
    __shared__ float wlist[NATOMS];
    __shared__ int   blist[NATOMS];
    __shared__ int   s_nnz;

    const int t = threadIdx.x;
    const int warp = t >> 5, lane = t & 31;
    const int P = blockIdx.y;
    const int a = blockIdx.z;

    if (t == 0) s_nnz = g_nnz[a];
    __syncthreads();
    const int nnz = s_nnz;

    const int rloc = t >> 1;
    const int eh   = (t & 1) * 32;

    if (nnz == 0) {
        float4 z = make_float4(0.f, 0.f, 0.f, 0.f);
#pragma unroll
        for (int h = 0; h < 2; h++) {
            int g = blockIdx.x * 256 + h * 128 + rloc;
            int q = g / 9, l = g - 9 * q;
            size_t grW = (size_t)(q * 18 + P * 9 + l);
            float4* d = (float4*)(out + (size_t)a * GK + grW * 64 + eh);
#pragma unroll
            for (int qq = 0; qq < 8; qq++) d[qq] = z;
        }
        return;
    }

    for (int i = t; i < 4096; i += 256) {
        int f = i >> 6, e = i & 63;
        wv16[f * PB + e] = g_Wvt16[(P << 12) + i];
    }
    if (t < nnz) { blist[t] = g_idx[a * NATOMS + t]; wlist[t] = g_wval[a * NATOMS + t]; }
    __syncthreads();

    const unsigned uy = (unsigned)__cvta_generic_to_shared(y16);
    const unsigned uw = (unsigned)__cvta_generic_to_shared(wv16);
    const int rowbase = warp * 16;
    const unsigned axoff = ((rowbase + (lane & 15)) * PB + (lane >> 4) * 8) * 2;
    const int lc = (lane & 3) * 2;
    const int raL = rowbase + (lane >> 2);

    for (int h = 0; h < 2; h++) {
        const int r0 = blockIdx.x * 256 + h * 128;
        size_t grW;
        {
            int g = r0 + rloc;
            int q = g / 9, l = g - 9 * q;
            grW = (size_t)(q * 18 + P * 9 + l);
        }

        {
            float acc[32];
#pragma unroll
            for (int i = 0; i < 32; i++) acc[i] = 0.0f;
            for (int j = 0; j < nnz; j++) {
                const uint4* src = (const uint4*)(g_xh + (size_t)blist[j] * GK + grW * 64 + eh);
                float w = wlist[j];
#pragma unroll
                for (int qq = 0; qq < 4; qq++) {
                    uint4 u = src[qq];
                    float2 f0 = __half22float2(*(__half2*)&u.x);
                    float2 f1 = __half22float2(*(__half2*)&u.y);
                    float2 f2 = __half22float2(*(__half2*)&u.z);
                    float2 f3 = __half22float2(*(__half2*)&u.w);
                    acc[qq*8+0] += w * f0.x; acc[qq*8+1] += w * f0.y;
                    acc[qq*8+2] += w * f1.x; acc[qq*8+3] += w * f1.y;
                    acc[qq*8+4] += w * f2.x; acc[qq*8+5] += w * f2.y;
                    acc[qq*8+6] += w * f3.x; acc[qq*8+7] += w * f3.y;
                }
            }
#pragma unroll
            for (int i = 0; i < 16; i++)
                *(unsigned*)(y16 + rloc * PB + eh + i * 2) = pack_h2(acc[2*i], acc[2*i+1]);
        }
        __syncthreads();

        float acc[8][4];
#pragma unroll
        for (int n = 0; n < 8; n++)
#pragma unroll
            for (int v = 0; v < 4; v++) acc[n][v] = 0.0f;

#pragma unroll
        for (int k = 0; k < 4; k++) {
            unsigned A[4];
            ldsm_x4(A, uy + axoff + k * 32);
#pragma unroll
            for (int n2 = 0; n2 < 4; n2++) {
                unsigned bo = ((n2 * 16 + (lane & 15)) * PB + (lane >> 4) * 8) * 2 + k * 32;
                unsigned B[4];
                ldsm_x4(B, uw + bo);
                mma_f16(acc[2*n2],   A, B[0], B[2]);
                mma_f16(acc[2*n2+1], A, B[1], B[3]);
            }
        }
#pragma unroll
        for (int n = 0; n < 8; n++) {
            int col = n * 8 + lc;
            *(float2*)(stgF + raL * FPITCH + col)       = make_float2(acc[n][0], acc[n][1]);
            *(float2*)(stgF + (raL + 8) * FPITCH + col) = make_float2(acc[n][2], acc[n][3]);
        }
        __syncthreads();
        {
            const float4* sF = (const float4*)(stgF + rloc * FPITCH + eh);
            float4* d = (float4*)(out + (size_t)a * GK + grW * 64 + eh);
#pragma unroll
            for (int qq = 0; qq < 8; qq++) d[qq] = sF[qq];
        }
        __syncthreads();
    }
}

// ---------------- launch ---------------------------------------------------------------
extern "C" void kernel_launch(void* const* d_in, const int* in_sizes, int n_in,
                              void* d_out, int out_size) {
    const float* x  = (const float*)d_in[0];
    const float* Wq = (const float*)d_in[1];
    const float* Wk = (const float*)d_in[2];
    const float* Wv = (const float*)d_in[3];
    float* out = (float*)d_out;
    (void)in_sizes; (void)n_in; (void)out_size;

    const int k2f_smem = (64 * PB + 2 * 128 * PB) * 2;                  // 46,080 B
    const int k3s_smem = K3_STAGES * (A_STAGE + B_STAGE);               // 55,296 B
    const int k6y_smem = (64 * PB + 128 * PB) * 2 + 128 * FPITCH * 4;   // 62,464 B
    cudaFuncSetAttribute(k2f,     cudaFuncAttributeMaxDynamicSharedMemorySize, k2f_smem);
    cudaFuncSetAttribute(k3s_dot, cudaFuncAttributeMaxDynamicSharedMemorySize, k3s_smem);
    cudaFuncSetAttribute(k6y,     cudaFuncAttributeMaxDynamicSharedMemorySize, k6y_smem);

    k0_zero<<<(NATOMS * NATOMS + 255) / 256, 256>>>();
    k1_M<<<(PDIM * FDIM * FDIM + 255) / 256, 256>>>(Wq, Wk, Wv);
    {
        dim3 grid(HROWS / 256, 2);                 // 2304 x 2 parities
        k2f<<<grid, 256, k2f_smem>>>(x);
    }
    {
        dim3 grid(2, 4, GK / K3_KCHUNK);           // 2 x 4 x 72 = 576 blocks
        k3s_dot<<<grid, 256, k3s_smem>>>();
    }
    k4b_close<<<NATOMS, NATOMS>>>();
    {
        dim3 grid(18, NATOMS);
        k5x_exact<<<grid, 256>>>(x);
    }
    k4_stats<<<NATOMS, NATOMS>>>();
    k5_compact<<<NATOMS, NATOMS>>>();
    {
        dim3 grid(PHROWS / 256, 2, NATOMS);        // 9 x 2 x 256
        k6y<<<grid, 256, k6y_smem>>>(out);
    }
}

// round 17
// speedup vs baseline: 1.0906x; 1.0906x over previous
#include <cuda_runtime.h>
#include <cuda_bf16.h>
#include <cuda_fp16.h>

#define NATOMS 256
#define PDIM 2
#define LDIM 9
#define FDIM 64
#define ROWLEN (PDIM*LDIM*FDIM)                 // 1152
#define GK (NATOMS*ROWLEN)                      // 294912
#define NROWS_TOTAL (NATOMS*NATOMS*PDIM*LDIM)   // 1,179,648 rows of 64
#define HROWS (NROWS_TOTAL/2)
#define PHROWS (NATOMS*LDIM)                    // 2304 parity-local rows per atom

// ---------------- scratch ------------------------------------------------------
__device__ __half g_Th[NATOMS * GK];            // fp16 T = x @ M
__device__ __half g_xh[NATOMS * GK];            // fp16 x
__device__ float  g_M[PDIM * FDIM * FDIM];      // fp32 M (exact recompute)
__device__ __half g_Mt16 [PDIM * FDIM * FDIM];  // Mt[p][f][e] fp16
__device__ __half g_Wvt16[PDIM * FDIM * FDIM];  // Wvt[p][f][e] fp16
__device__ float g_dotb[NATOMS * NATOMS];
__device__ float g_cmax[NATOMS];
__device__ float g_csum[NATOMS];
__device__ int   g_idx[NATOMS * NATOMS];
__device__ float g_wval[NATOMS * NATOMS];
__device__ int   g_nnz[NATOMS];
__device__ int   g_ccol[NATOMS];
__device__ int   g_calist[NATOMS * 8];
__device__ int   g_cak[NATOMS];
__device__ int   g_nccols;

extern __shared__ __half smdyn[];

// ---------------- K0 ------------------------------------------------------------
__global__ void k0_zero() {
    int i = blockIdx.x * blockDim.x + threadIdx.x;
    if (i < NATOMS * NATOMS) g_dotb[i] = 0.0f;
    if (i < NATOMS) g_nnz[i] = 0;
    if (i == 0) g_nccols = 0;
}

// ---------------- K1: M fp32 + Mt/Wvt fp16 transposed ----------------------------
__global__ void k1_M(const float* __restrict__ Wq, const float* __restrict__ Wk,
                     const float* __restrict__ Wv) {
    int id = blockIdx.x * blockDim.x + threadIdx.x;
    if (id >= PDIM * FDIM * FDIM) return;
    int p = id >> 12;
    int e = (id >> 6) & 63;
    int f = id & 63;
    const float* q = Wq + (p << 12) + (e << 6);
    const float* k = Wk + (p << 12) + (f << 6);
    float s = 0.0f;
#pragma unroll 16
    for (int g = 0; g < 64; g++) s += q[g] * k[g];
    g_M[id] = s;

    int tid = (p << 12) + (f << 6) + e;   // transposed [p][f][e]
    g_Mt16[tid]  = __float2half_rn(s);
    g_Wvt16[tid] = __float2half_rn(Wv[id]);
}

// ---------------- helpers --------------------------------------------------------
static __device__ __forceinline__ void cpa16(unsigned sdst, const void* gsrc) {
    asm volatile("cp.async.cg.shared.global [%0], [%1], 16;\n" :: "r"(sdst), "l"(gsrc));
}
static __device__ __forceinline__ void ldsm_x4(unsigned r[4], unsigned addr) {
    asm volatile("ldmatrix.sync.aligned.m8n8.x4.shared.b16 {%0,%1,%2,%3}, [%4];\n"
        : "=r"(r[0]), "=r"(r[1]), "=r"(r[2]), "=r"(r[3]) : "r"(addr));
}
static __device__ __forceinline__ void mma_f16(float d[4], const unsigned a[4],
                                               const unsigned b0, const unsigned b1) {
    asm volatile("mma.sync.aligned.m16n8k16.row.col.f32.f16.f16.f32 "
        "{%0,%1,%2,%3},{%4,%5,%6,%7},{%8,%9},{%0,%1,%2,%3};\n"
        : "+f"(d[0]), "+f"(d[1]), "+f"(d[2]), "+f"(d[3])
        : "r"(a[0]), "r"(a[1]), "r"(a[2]), "r"(a[3]), "r"(b0), "r"(b1));
}
static __device__ __forceinline__ unsigned pack_h2(float a, float b) {
    __half2 h2 = __floats2half2_rn(a, b);
    return *reinterpret_cast<unsigned*>(&h2);
}

#define PB 72   // smem pitch (16-bit elems): 144B rows -> conflict-free ldsm

// ---------------- K2F: parity-sorted T = x@M + xh emit (256 rows/block, occ 3) -----
__global__ __launch_bounds__(256, 3) void k2f(const float* __restrict__ x) {
    __half* mt16 = smdyn;                 // [64][PB]
    __half* x16  = mt16 + 64 * PB;        // [128][PB]
    __half* stgT = x16 + 128 * PB;        // [128][PB]

    const int t = threadIdx.x;
    const int warp = t >> 5, lane = t & 31;
    const int P = blockIdx.y;

    for (int i = t; i < 4096; i += 256) {
        int f = i >> 6, e = i & 63;
        mt16[f * PB + e] = g_Mt16[(P << 12) + i];
    }

    const int rloc = t >> 1;
    const int eh   = (t & 1) * 32;
    const int rowbase = warp * 16;
    const unsigned axoff = ((rowbase + (lane & 15)) * PB + (lane >> 4) * 8) * 2;
    const int lc = (lane & 3) * 2;
    const int raL = rowbase + (lane >> 2);

    const unsigned ux = (unsigned)__cvta_generic_to_shared(x16);
    const unsigned um = (unsigned)__cvta_generic_to_shared(mt16);

    for (int h = 0; h < 2; h++) {
        const int r0 = blockIdx.x * 256 + h * 128;
        __syncthreads();

        size_t grW;
        {
            int g = r0 + rloc;
            int q = g / 9, l = g - 9 * q;
            grW = (size_t)(q * 18 + P * 9 + l);
            const float* gx = x + grW * 64 + eh;
            unsigned hx[16];
#pragma unroll
            for (int qq = 0; qq < 8; qq++) {
                float4 v = *(const float4*)(gx + qq * 4);
                unsigned h01 = pack_h2(v.x, v.y), h23 = pack_h2(v.z, v.w);
                hx[qq * 2] = h01; hx[qq * 2 + 1] = h23;
                *(unsigned*)(x16 + rloc * PB + eh + qq * 4)     = h01;
                *(unsigned*)(x16 + rloc * PB + eh + qq * 4 + 2) = h23;
            }
            uint4* dh = (uint4*)(g_xh + grW * 64 + eh);
#pragma unroll
            for (int qq = 0; qq < 4; qq++)
                dh[qq] = make_uint4(hx[4*qq], hx[4*qq+1], hx[4*qq+2], hx[4*qq+3]);
        }
        __syncthreads();

        float accT[8][4];
#pragma unroll
        for (int n = 0; n < 8; n++)
#pragma unroll
            for (int v = 0; v < 4; v++) accT[n][v] = 0.0f;

#pragma unroll
        for (int k = 0; k < 4; k++) {
            unsigned A[4];
            ldsm_x4(A, ux + axoff + k * 32);
#pragma unroll
            for (int n2 = 0; n2 < 4; n2++) {
                unsigned bo = ((n2 * 16 + (lane & 15)) * PB + (lane >> 4) * 8) * 2 + k * 32;
                unsigned B[4];
                ldsm_x4(B, um + bo);
                mma_f16(accT[2*n2],   A, B[0], B[2]);
                mma_f16(accT[2*n2+1], A, B[1], B[3]);
            }
        }
#pragma unroll
        for (int n = 0; n < 8; n++) {
            int col = n * 8 + lc;
            *(unsigned*)(stgT + raL * PB + col)       = pack_h2(accT[n][0], accT[n][1]);
            *(unsigned*)(stgT + (raL + 8) * PB + col) = pack_h2(accT[n][2], accT[n][3]);
        }
        __syncthreads();
        {
            const uint4* sT = (const uint4*)(stgT + rloc * PB + eh);
            uint4* dT = (uint4*)(g_Th + grW * 64 + eh);
#pragma unroll
            for (int qq = 0; qq < 4; qq++) dT[qq] = sT[qq];
        }
    }
}

// ---------------- K3s: dotb = Th * xh^T (fp16; 32-k stages, 128x128, occ 2) -------
#define K3_KCHUNK 4096
#define K3_STAGES 4                       // each stage = 2 x 16-k pieces
#define PITCH 24
#define PIECE_BYTES (128 * PITCH * 2)     // 6144
#define STAGE2_BYTES (2 * PIECE_BYTES)    // 12288
#define STAGE2_ELEMS (2 * 128 * PITCH)

__global__ __launch_bounds__(256, 2) void k3s_dot() {
    __half* As = smdyn;                                   // [4][STAGE2_ELEMS]
    __half* Bs = As + K3_STAGES * STAGE2_ELEMS;

    const int t = threadIdx.x;
    const int m0 = blockIdx.x * 128, n0 = blockIdx.y * 128;
    const size_t kb = (size_t)blockIdx.z * K3_KCHUNK;

    const unsigned uA = (unsigned)__cvta_generic_to_shared(As);
    const unsigned uB = (unsigned)__cvta_generic_to_shared(Bs);

    const int row = t >> 1, half = t & 1;
    const size_t goff = (size_t)row * GK + kb + half * 8;
    const __half* ga = g_Th + (size_t)m0 * GK + goff;
    const __half* gb = g_xh + (size_t)n0 * GK + goff;
    const unsigned soff = (row * PITCH + half * 8) * 2;

    const int NS2 = K3_KCHUNK / 32;       // 128 iterations

#pragma unroll
    for (int s = 0; s < K3_STAGES - 1; s++) {
#pragma unroll
        for (int p = 0; p < 2; p++) {
            cpa16(uA + soff + s * STAGE2_BYTES + p * PIECE_BYTES, ga + (size_t)(s * 2 + p) * 16);
            cpa16(uB + soff + s * STAGE2_BYTES + p * PIECE_BYTES, gb + (size_t)(s * 2 + p) * 16);
        }
        asm volatile("cp.async.commit_group;\n");
    }

    const int warp = t >> 5, lane = t & 31;
    const int wm = warp >> 2, wn = warp & 3;
    const unsigned aoff = ((wm * 64 + (lane & 15)) * PITCH + (lane >> 4) * 8) * 2;
    const unsigned boff = ((wn * 32 + (lane & 15)) * PITCH + (lane >> 4) * 8) * 2;

    float acc[4][4][4] = {};

    int buf = 0, pbuf = K3_STAGES - 1;
    for (int ks = 0; ks < NS2; ks++) {
        asm volatile("cp.async.wait_group %0;\n" :: "n"(K3_STAGES - 2));
        __syncthreads();

#pragma unroll
        for (int p = 0; p < 2; p++) {
            const unsigned base = buf * STAGE2_BYTES + p * PIECE_BYTES;
            unsigned bh[2][4];
#pragma unroll
            for (int j = 0; j < 2; j++)
                ldsm_x4(bh[j], uB + boff + base + j * 16 * PITCH * 2);
#pragma unroll
            for (int i = 0; i < 4; i++) {
                unsigned ah[4];
                ldsm_x4(ah, uA + aoff + base + i * 16 * PITCH * 2);
#pragma unroll
                for (int j = 0; j < 4; j++) {
                    unsigned b0 = bh[j >> 1][(j & 1)], b1 = bh[j >> 1][(j & 1) + 2];
                    mma_f16(acc[i][j], ah, b0, b1);
                }
            }
        }

        const int pf = ks + K3_STAGES - 1;
        if (pf < NS2) {
#pragma unroll
            for (int p = 0; p < 2; p++) {
                cpa16(uA + soff + pbuf * STAGE2_BYTES + p * PIECE_BYTES, ga + (size_t)(pf * 2 + p) * 16);
                cpa16(uB + soff + pbuf * STAGE2_BYTES + p * PIECE_BYTES, gb + (size_t)(pf * 2 + p) * 16);
            }
        }
        asm volatile("cp.async.commit_group;\n");
        buf  = (buf  == K3_STAGES - 1) ? 0 : buf  + 1;
        pbuf = (pbuf == K3_STAGES - 1) ? 0 : pbuf + 1;
    }
    asm volatile("cp.async.wait_group 0;\n");

    const int lr = lane >> 2, lc = (lane & 3) * 2;
#pragma unroll
    for (int i = 0; i < 4; i++)
#pragma unroll
        for (int j = 0; j < 4; j++) {
            int r = m0 + wm * 64 + i * 16 + lr;
            int c = n0 + wn * 32 + j * 8 + lc;
            atomicAdd(&g_dotb[r * NATOMS + c],           acc[i][j][0]);
            atomicAdd(&g_dotb[r * NATOMS + c + 1],       acc[i][j][1]);
            atomicAdd(&g_dotb[(r + 8) * NATOMS + c],     acc[i][j][2]);
            atomicAdd(&g_dotb[(r + 8) * NATOMS + c + 1], acc[i][j][3]);
        }
}

// ---------------- K4b: columns with >=2 entries within margin ----------------------
#define CLOSE_MARGIN 14.0f
__global__ void k4b_close() {
    int c = blockIdx.x, t = threadIdx.x;
    __shared__ float red[256];
    __shared__ int cnt, pos;
    if (t == 0) { cnt = 0; pos = 0; }
    float v = g_dotb[t * NATOMS + c];
    red[t] = v; __syncthreads();
    for (int s = 128; s > 0; s >>= 1) {
        if (t < s) red[t] = fmaxf(red[t], red[t + s]);
        __syncthreads();
    }
    float mx = red[0];
    bool cand = (v >= mx - CLOSE_MARGIN);
    if (cand) atomicAdd(&cnt, 1);
    __syncthreads();
    if (cnt >= 2) {
        if (t == 0) { int s = atomicAdd(&g_nccols, 1); g_ccol[s] = c; }
        if (cand) {
            int p = atomicAdd(&pos, 1);
            if (p < 8) { g_calist[c * 8 + p] = t; g_dotb[t * NATOMS + c] = 0.0f; }
        }
        __syncthreads();
        if (t == 0) g_cak[c] = (cnt < 8) ? cnt : 8;
    }
}

// ---------------- K5x: exact fp32 logits for close columns -------------------------
__global__ __launch_bounds__(256) void k5x_exact(const float* __restrict__ x) {
    __shared__ float Msh[2 * 4096];
    __shared__ float red[256];
    int s = blockIdx.y;
    if (s >= g_nccols) return;
    int t = threadIdx.x;
    int c = g_ccol[s];
    int ka = g_cak[c];

    for (int i = t; i < 8192 / 4; i += 256)
        ((float4*)Msh)[i] = ((const float4*)g_M)[i];
    __syncthreads();

    int row = blockIdx.x * 256 + t;
    int p = (row / LDIM) & 1;
    const float* Mp = Msh + (p << 12);

    float xc[64];
    {
        const float4* xcp = (const float4*)(x + (size_t)c * GK + (size_t)row * 64);
#pragma unroll
        for (int i = 0; i < 16; i++) {
            float4 v = xcp[i];
            xc[4*i] = v.x; xc[4*i+1] = v.y; xc[4*i+2] = v.z; xc[4*i+3] = v.w;
        }
    }
    float z[64];
#pragma unroll 4
    for (int e = 0; e < 64; e++) {
        const float4* Mr = (const float4*)(Mp + e * 64);
        float sm = 0.0f;
#pragma unroll
        for (int f4 = 0; f4 < 16; f4++) {
            float4 m = Mr[f4];
            sm += m.x * xc[4*f4] + m.y * xc[4*f4+1] + m.z * xc[4*f4+2] + m.w * xc[4*f4+3];
        }
        z[e] = sm;
    }

    for (int j = 0; j < ka; j++) {
        int a = g_calist[c * 8 + j];
        const float4* xap = (const float4*)(x + (size_t)a * GK + (size_t)row * 64);
        float sd = 0.0f;
#pragma unroll
        for (int i = 0; i < 16; i++) {
            float4 v = xap[i];
            sd += v.x * z[4*i] + v.y * z[4*i+1] + v.z * z[4*i+2] + v.w * z[4*i+3];
        }
        red[t] = sd; __syncthreads();
        for (int st = 128; st > 0; st >>= 1) {
            if (t < st) red[t] += red[t + st];
            __syncthreads();
        }
        if (t == 0) atomicAdd(&g_dotb[a * NATOMS + c], red[0]);
        __syncthreads();
    }
}

// ---------------- K4s: per-column softmax stats (max, sum) -------------------------
__global__ void k4_stats() {
    int c = blockIdx.x, t = threadIdx.x;
    __shared__ float red[256];
    float v = g_dotb[t * NATOMS + c];
    red[t] = v; __syncthreads();
    for (int s = 128; s > 0; s >>= 1) {
        if (t < s) red[t] = fmaxf(red[t], red[t + s]);
        __syncthreads();
    }
    float mx = red[0]; __syncthreads();
    float e = expf(v - mx);
    red[t] = e; __syncthreads();
    for (int s = 128; s > 0; s >>= 1) {
        if (t < s) red[t] += red[t + s];
        __syncthreads();
    }
    if (t == 0) { g_cmax[c] = mx; g_csum[c] = red[0]; }
}

// ---------------- K5: compact significant weights (softmax inline) -----------------
__global__ void k5_compact() {
    int a = blockIdx.x, t = threadIdx.x;
    float wv = expf(g_dotb[a * NATOMS + t] - g_cmax[t]) / g_csum[t];
    bool nz = (wv > 1e-7f);
    unsigned m = __ballot_sync(0xffffffffu, nz);
    int lane = t & 31, warp = t >> 5;
    int pre = __popc(m & ((1u << lane) - 1u));
    __shared__ int wcnt[8], woff[8];
    if (lane == 0) wcnt[warp] = __popc(m);
    __syncthreads();
    if (t == 0) {
        int s = 0;
        for (int i = 0; i < 8; i++) { woff[i] = s; s += wcnt[i]; }
        g_nnz[a] = s;
    }
    __syncthreads();
    if (nz) {
        int pos = woff[warp] + pre;
        g_idx[a * NATOMS + pos]  = t;
        g_wval[a * NATOMS + pos] = wv;
    }
}

// ---------------- K6Y: out[a] = (sum_j w_j xh[b_j]) @ Wv  (256 rows/block, occ 3) ---
#define FPITCH 68   // fp32 staging pitch

__global__ __launch_bounds__(256, 3) void k6y(float* __restrict__ out) {
    __half* wv16 = smdyn;                  // [64][PB]
    __half* y16  = wv16 + 64 * PB;         // [128][PB]
    float*  stgF = (float*)(y16 + 128 * PB);   // [128][FPITCH]
    __shared__ float wlist[NATOMS];
    __shared__ int   blist[NATOMS];
    __shared__ int   s_nnz;

    const int t = threadIdx.x;
    const int warp = t >> 5, lane = t & 31;
    const int P = blockIdx.y;
    const int a = blockIdx.z;

    if (t == 0) s_nnz = g_nnz[a];
    __syncthreads();
    const int nnz = s_nnz;

    const int rloc = t >> 1;
    const int eh   = (t & 1) * 32;

    if (nnz == 0) {
        float4 z = make_float4(0.f, 0.f, 0.f, 0.f);
#pragma unroll
        for (int h = 0; h < 2; h++) {
            int g = blockIdx.x * 256 + h * 128 + rloc;
            int q = g / 9, l = g - 9 * q;
            size_t grW = (size_t)(q * 18 + P * 9 + l);
            float4* d = (float4*)(out + (size_t)a * GK + grW * 64 + eh);
#pragma unroll
            for (int qq = 0; qq < 8; qq++) d[qq] = z;
        }
        return;
    }

    for (int i = t; i < 4096; i += 256) {
        int f = i >> 6, e = i & 63;
        wv16[f * PB + e] = g_Wvt16[(P << 12) + i];
    }
    if (t < nnz) { blist[t] = g_idx[a * NATOMS + t]; wlist[t] = g_wval[a * NATOMS + t]; }
    __syncthreads();

    const unsigned uy = (unsigned)__cvta_generic_to_shared(y16);
    const unsigned uw = (unsigned)__cvta_generic_to_shared(wv16);
    const int rowbase = warp * 16;
    const unsigned axoff = ((rowbase + (lane & 15)) * PB + (lane >> 4) * 8) * 2;
    const int lc = (lane & 3) * 2;
    const int raL = rowbase + (lane >> 2);

    for (int h = 0; h < 2; h++) {
        const int r0 = blockIdx.x * 256 + h * 128;
        size_t grW;
        {
            int g = r0 + rloc;
            int q = g / 9, l = g - 9 * q;
            grW = (size_t)(q * 18 + P * 9 + l);
        }

        {
            float acc[32];
#pragma unroll
            for (int i = 0; i < 32; i++) acc[i] = 0.0f;
            for (int j = 0; j < nnz; j++) {
                const uint4* src = (const uint4*)(g_xh + (size_t)blist[j] * GK + grW * 64 + eh);
                float w = wlist[j];
#pragma unroll
                for (int qq = 0; qq < 4; qq++) {
                    uint4 u = src[qq];
                    float2 f0 = __half22float2(*(__half2*)&u.x);
                    float2 f1 = __half22float2(*(__half2*)&u.y);
                    float2 f2 = __half22float2(*(__half2*)&u.z);
                    float2 f3 = __half22float2(*(__half2*)&u.w);
                    acc[qq*8+0] += w * f0.x; acc[qq*8+1] += w * f0.y;
                    acc[qq*8+2] += w * f1.x; acc[qq*8+3] += w * f1.y;
                    acc[qq*8+4] += w * f2.x; acc[qq*8+5] += w * f2.y;
                    acc[qq*8+6] += w * f3.x; acc[qq*8+7] += w * f3.y;
                }
            }
#pragma unroll
            for (int i = 0; i < 16; i++)
                *(unsigned*)(y16 + rloc * PB + eh + i * 2) = pack_h2(acc[2*i], acc[2*i+1]);
        }
        __syncthreads();

        float acc[8][4];
#pragma unroll
        for (int n = 0; n < 8; n++)
#pragma unroll
            for (int v = 0; v < 4; v++) acc[n][v] = 0.0f;

#pragma unroll
        for (int k = 0; k < 4; k++) {
            unsigned A[4];
            ldsm_x4(A, uy + axoff + k * 32);
#pragma unroll
            for (int n2 = 0; n2 < 4; n2++) {
                unsigned bo = ((n2 * 16 + (lane & 15)) * PB + (lane >> 4) * 8) * 2 + k * 32;
                unsigned B[4];
                ldsm_x4(B, uw + bo);
                mma_f16(acc[2*n2],   A, B[0], B[2]);
                mma_f16(acc[2*n2+1], A, B[1], B[3]);
            }
        }
#pragma unroll
        for (int n = 0; n < 8; n++) {
            int col = n * 8 + lc;
            *(float2*)(stgF + raL * FPITCH + col)       = make_float2(acc[n][0], acc[n][1]);
            *(float2*)(stgF + (raL + 8) * FPITCH + col) = make_float2(acc[n][2], acc[n][3]);
        }
        __syncthreads();
        {
            const float4* sF = (const float4*)(stgF + rloc * FPITCH + eh);
            float4* d = (float4*)(out + (size_t)a * GK + grW * 64 + eh);
#pragma unroll
            for (int qq = 0; qq < 8; qq++) d[qq] = sF[qq];
        }
        __syncthreads();
    }
}

// ---------------- launch ---------------------------------------------------------------
extern "C" void kernel_launch(void* const* d_in, const int* in_sizes, int n_in,
                              void* d_out, int out_size) {
    const float* x  = (const float*)d_in[0];
    const float* Wq = (const float*)d_in[1];
    const float* Wk = (const float*)d_in[2];
    const float* Wv = (const float*)d_in[3];
    float* out = (float*)d_out;
    (void)in_sizes; (void)n_in; (void)out_size;

    const int k2f_smem = (64 * PB + 2 * 128 * PB) * 2;                  // 46,080 B
    const int k3s_smem = 2 * K3_STAGES * STAGE2_BYTES;                  // 98,304 B
    const int k6y_smem = (64 * PB + 128 * PB) * 2 + 128 * FPITCH * 4;   // 62,464 B
    cudaFuncSetAttribute(k2f,     cudaFuncAttributeMaxDynamicSharedMemorySize, k2f_smem);
    cudaFuncSetAttribute(k3s_dot, cudaFuncAttributeMaxDynamicSharedMemorySize, k3s_smem);
    cudaFuncSetAttribute(k6y,     cudaFuncAttributeMaxDynamicSharedMemorySize, k6y_smem);

    k0_zero<<<(NATOMS * NATOMS + 255) / 256, 256>>>();
    k1_M<<<(PDIM * FDIM * FDIM + 255) / 256, 256>>>(Wq, Wk, Wv);
    {
        dim3 grid(HROWS / 256, 2);                 // 2304 x 2 parities
        k2f<<<grid, 256, k2f_smem>>>(x);
    }
    {
        dim3 grid(2, 2, GK / K3_KCHUNK);           // 2 x 2 x 72 = 288 blocks
        k3s_dot<<<grid, 256, k3s_smem>>>();
    }
    k4b_close<<<NATOMS, NATOMS>>>();
    {
        dim3 grid(18, NATOMS);
        k5x_exact<<<grid, 256>>>(x);
    }
    k4_stats<<<NATOMS, NATOMS>>>();
    k5_compact<<<NATOMS, NATOMS>>>();
    {
        dim3 grid(PHROWS / 256, 2, NATOMS);        // 9 x 2 x 256
        k6y<<<grid, 256, k6y_smem>>>(out);
    }
}